// round 13
// baseline (speedup 1.0000x reference)
#include <cuda_runtime.h>
#include <math.h>

// Problem constants
//  B=8, N=4096 (64x64), C=384, heads=6, d=64, G=3*heads=18
#define NB   8
#define NN   4096
#define NC   384
#define ND   64
#define NG   18

// Scratch (static device globals — allowed; no runtime allocation)
// g_qkv2[b][k][g*4096+n] : QKV projections in "reshape-linear" layout.
//   For pixel m, mix-tap i:  f_all[b,i,m,k] = g_qkv2[b][k][m*18+i]
__device__ float g_qkv2[(size_t)NB * ND * NG * NN];   // 151 MB
// g_yc[b][c][n] : conv output, channel-major (coalesced conv writes)
__device__ float g_yc[(size_t)NB * NC * NN];          // 50 MB
// g_ya[b*n][c]  : LN+GELU output, token-major rows for proj GEMM
__device__ float g_ya[(size_t)NB * NN * NC];          // 50 MB

// ---------------------------------------------------------------------------
// GEMM1: y3[m, oc] = x[m,:] . W3[oc,:] + b3[oc],  W3 = concat(q_w, kv_w)
// M = 32768, Nout = 1152, K = 384.  128x128x8 tiles, 8x8 per thread.
// Epilogue scatters into g_qkv2 via smem staging (coalesced 512B runs):
//   g = oc/64, k = oc%64  ->  g_qkv2[((b*64+k)*18+g)*4096 + n]
// ---------------------------------------------------------------------------
__global__ void __launch_bounds__(256) k_gemm_qkv(
    const float* __restrict__ x,
    const float* __restrict__ qw, const float* __restrict__ kvw,
    const float* __restrict__ qb, const float* __restrict__ kvb)
{
    const int K = NC;
    const int n0 = blockIdx.x * 128;   // 0..1024, step 128
    const int m0 = blockIdx.y * 128;

    const float* W;
    int nrow0;
    if (n0 < 384) { W = qw;  nrow0 = n0; }
    else          { W = kvw; nrow0 = n0 - 384; }

    __shared__ float As[8][132];
    __shared__ float Ws[8][132];
    __shared__ float Cs[128][17];

    const int tid  = threadIdx.x;
    const int tx   = tid & 15;
    const int ty   = tid >> 4;
    const int lrow = tid >> 1;
    const int lk4  = (tid & 1) * 4;

    const float* Ap = x + (size_t)(m0 + lrow) * K + lk4;
    const float* Wp = W + (size_t)(nrow0 + lrow) * K + lk4;

    float acc[8][8];
#pragma unroll
    for (int i = 0; i < 8; i++)
#pragma unroll
        for (int j = 0; j < 8; j++) acc[i][j] = 0.f;

#pragma unroll 1
    for (int kt = 0; kt < K; kt += 8) {
        float4 av = *(const float4*)(Ap + kt);
        float4 wv = *(const float4*)(Wp + kt);
        As[lk4 + 0][lrow] = av.x; As[lk4 + 1][lrow] = av.y;
        As[lk4 + 2][lrow] = av.z; As[lk4 + 3][lrow] = av.w;
        Ws[lk4 + 0][lrow] = wv.x; Ws[lk4 + 1][lrow] = wv.y;
        Ws[lk4 + 2][lrow] = wv.z; Ws[lk4 + 3][lrow] = wv.w;
        __syncthreads();
#pragma unroll
        for (int kk = 0; kk < 8; kk++) {
            float4 a0 = *(const float4*)&As[kk][ty * 4];
            float4 a1 = *(const float4*)&As[kk][64 + ty * 4];
            float4 b0 = *(const float4*)&Ws[kk][tx * 4];
            float4 b1 = *(const float4*)&Ws[kk][64 + tx * 4];
            float a[8]  = {a0.x, a0.y, a0.z, a0.w, a1.x, a1.y, a1.z, a1.w};
            float bv[8] = {b0.x, b0.y, b0.z, b0.w, b1.x, b1.y, b1.z, b1.w};
#pragma unroll
            for (int i = 0; i < 8; i++)
#pragma unroll
                for (int j = 0; j < 8; j++) acc[i][j] += a[i] * bv[j];
        }
        __syncthreads();
    }

    // Staged scatter epilogue: 8 passes of 128 rows x 16 cols through smem.
#pragma unroll 1
    for (int jj = 0; jj < 8; jj++) {
        const int half = jj >> 2;
        const int jl   = jj & 3;
#pragma unroll
        for (int i = 0; i < 8; i++) {
            int mrow = (i < 4) ? (ty * 4 + i) : (64 + ty * 4 + (i - 4));
            Cs[mrow][tx] = acc[i][half * 4 + jl];
        }
        __syncthreads();
#pragma unroll
        for (int p = tid; p < 2048; p += 256) {
            int col16 = p >> 7;
            int ml    = p & 127;
            int oc    = n0 + half * 64 + col16 * 4 + jl;      // 0..1151
            float bvv = (oc < 384) ? __ldg(qb + oc) : __ldg(kvb + oc - 384);
            int m = m0 + ml;
            int bi = m >> 12;        // batch
            int n  = m & 4095;       // token within batch
            int g  = oc >> 6;        // qkv group 0..17
            int kd = oc & 63;        // head-dim index
            g_qkv2[(((size_t)(bi * 64 + kd)) * 18 + g) * 4096 + n] = Cs[ml][col16] + bvv;
        }
        __syncthreads();
    }
}

// ---------------------------------------------------------------------------
// Fused 1x1 fc mix + grouped 3x3 conv.
// Block = (b, k, 16-row tile). Builds f[o=0..8][18 rows][66 cols] in smem
// directly from g_qkv2 (record m*18..m*18+17 per pixel), then 3x3 conv
// producing 6 output channels (oc = k*6+j), written channel-major to g_yc.
// ---------------------------------------------------------------------------
__global__ void __launch_bounds__(256) k_fc_conv(
    const float* __restrict__ fcw, const float* __restrict__ fcb,
    const float* __restrict__ depw, const float* __restrict__ depb)
{
    const int h0 = blockIdx.x * 16;
    const int k  = blockIdx.y;
    const int b  = blockIdx.z;

    __shared__ float fs[9][18][66];
    __shared__ float fw[162];   // fc_w [9][18]
    __shared__ float fb9[9];
    __shared__ float ws[6][81]; // dep_w for the 6 output channels of this group
    __shared__ float wb[6];

    const int tid = threadIdx.x;
    if (tid < 162) fw[tid] = fcw[tid];
    if (tid < 9)   fb9[tid] = fcb[tid];
    if (tid < 6)   wb[tid] = depb[k * 6 + tid];
    for (int p = tid; p < 486; p += 256) ws[p / 81][p % 81] = depw[(size_t)(k * 6) * 81 + p];

    float* fsf = &fs[0][0][0];
    for (int p = tid; p < 9 * 18 * 66; p += 256) fsf[p] = 0.f;
    __syncthreads();

    const float* base = g_qkv2 + ((size_t)(b * 64 + k)) * (NG * NN);

    // fc phase: 18 rows (h0-1 .. h0+16) x 64 cols; out-of-range rows stay 0.
    for (int p = tid; p < 18 * 64; p += 256) {
        int r = p >> 6;
        int c = p & 63;
        int h = h0 - 1 + r;
        if (h >= 0 && h < 64) {
            const float* src = base + (size_t)(h * 64 + c) * 18;
            float a9[9];
#pragma unroll
            for (int o = 0; o < 9; o++) a9[o] = fb9[o];
#pragma unroll
            for (int i = 0; i < 18; i++) {
                float v = src[i];
#pragma unroll
                for (int o = 0; o < 9; o++) a9[o] += fw[o * 18 + i] * v;
            }
#pragma unroll
            for (int o = 0; o < 9; o++) fs[o][r][c + 1] = a9[o];
        }
    }
    __syncthreads();

    // conv phase: each thread does 4 output rows x 1 col x 6 output channels
    const int c  = tid & 63;
    const int r0 = (tid >> 6) * 4;
    float acc[4][6];
#pragma unroll
    for (int rr = 0; rr < 4; rr++)
#pragma unroll
        for (int j = 0; j < 6; j++) acc[rr][j] = wb[j];

#pragma unroll
    for (int o = 0; o < 9; o++) {
#pragma unroll
        for (int dy = 0; dy < 3; dy++) {
#pragma unroll
            for (int dx = 0; dx < 3; dx++) {
                const int wi = o * 9 + dy * 3 + dx;
                float w0 = ws[0][wi], w1 = ws[1][wi], w2 = ws[2][wi];
                float w3 = ws[3][wi], w4 = ws[4][wi], w5 = ws[5][wi];
#pragma unroll
                for (int rr = 0; rr < 4; rr++) {
                    float fv = fs[o][r0 + rr + dy][c + dx];
                    acc[rr][0] += fv * w0; acc[rr][1] += fv * w1;
                    acc[rr][2] += fv * w2; acc[rr][3] += fv * w3;
                    acc[rr][4] += fv * w4; acc[rr][5] += fv * w5;
                }
            }
        }
    }

#pragma unroll
    for (int j = 0; j < 6; j++) {
        size_t chbase = ((size_t)(b * NC + k * 6 + j)) * NN;
#pragma unroll
        for (int rr = 0; rr < 4; rr++)
            g_yc[chbase + (h0 + r0 + rr) * 64 + c] = acc[rr][j];
    }
}

// ---------------------------------------------------------------------------
// Transpose + LayerNorm + exact GELU.
// Block = (16 tokens, batch b). smem tile s[384][17] (conflict-free).
// Reads g_yc channel-major coalesced, writes g_ya token-major coalesced.
// ---------------------------------------------------------------------------
__global__ void __launch_bounds__(256) k_ln_gelu(
    const float* __restrict__ lng, const float* __restrict__ lnb)
{
    const int m0 = blockIdx.x * 16;
    const int b  = blockIdx.y;
    __shared__ float s[NC][17];

    const int tid = threadIdx.x;
    for (int p = tid; p < NC * 16; p += 256) {
        int ch = p >> 4;
        int ml = p & 15;
        s[ch][ml] = g_yc[((size_t)(b * NC + ch)) * NN + m0 + ml];
    }
    __syncthreads();

    const int w    = tid >> 5;
    const int lane = tid & 31;
#pragma unroll
    for (int tt = 0; tt < 2; tt++) {
        int t = w * 2 + tt;
        float sum = 0.f, sq = 0.f;
#pragma unroll
        for (int ch = lane; ch < NC; ch += 32) {
            float v = s[ch][t];
            sum += v;
            sq  += v * v;
        }
#pragma unroll
        for (int off = 16; off > 0; off >>= 1) {
            sum += __shfl_xor_sync(0xffffffffu, sum, off);
            sq  += __shfl_xor_sync(0xffffffffu, sq,  off);
        }
        float mean = sum * (1.f / NC);
        float var  = sq * (1.f / NC) - mean * mean;
        float rstd = rsqrtf(var + 1e-5f);
        size_t orow = ((size_t)(b * NN + m0 + t)) * NC;
#pragma unroll
        for (int ch = lane; ch < NC; ch += 32) {
            float v  = (s[ch][t] - mean) * rstd * __ldg(lng + ch) + __ldg(lnb + ch);
            float gl = 0.5f * v * (1.f + erff(v * 0.70710678118654752f));
            g_ya[orow + ch] = gl;
        }
    }
}

// ---------------------------------------------------------------------------
// GEMM2: out[m, c] = g_ya[m,:] . proj_w[c,:] + proj_b[c]
// M = 32768, Nout = 384, K = 384. Same tile scheme, float4 direct epilogue.
// ---------------------------------------------------------------------------
__global__ void __launch_bounds__(256) k_gemm_proj(
    const float* __restrict__ W, const float* __restrict__ bias,
    float* __restrict__ out)
{
    const int K  = NC;
    const int n0 = blockIdx.x * 128;
    const int m0 = blockIdx.y * 128;

    __shared__ float As[8][132];
    __shared__ float Ws[8][132];

    const int tid  = threadIdx.x;
    const int tx   = tid & 15;
    const int ty   = tid >> 4;
    const int lrow = tid >> 1;
    const int lk4  = (tid & 1) * 4;

    const float* Ap = g_ya + (size_t)(m0 + lrow) * K + lk4;
    const float* Wp = W    + (size_t)(n0 + lrow) * K + lk4;

    float acc[8][8];
#pragma unroll
    for (int i = 0; i < 8; i++)
#pragma unroll
        for (int j = 0; j < 8; j++) acc[i][j] = 0.f;

#pragma unroll 1
    for (int kt = 0; kt < K; kt += 8) {
        float4 av = *(const float4*)(Ap + kt);
        float4 wv = *(const float4*)(Wp + kt);
        As[lk4 + 0][lrow] = av.x; As[lk4 + 1][lrow] = av.y;
        As[lk4 + 2][lrow] = av.z; As[lk4 + 3][lrow] = av.w;
        Ws[lk4 + 0][lrow] = wv.x; Ws[lk4 + 1][lrow] = wv.y;
        Ws[lk4 + 2][lrow] = wv.z; Ws[lk4 + 3][lrow] = wv.w;
        __syncthreads();
#pragma unroll
        for (int kk = 0; kk < 8; kk++) {
            float4 a0 = *(const float4*)&As[kk][ty * 4];
            float4 a1 = *(const float4*)&As[kk][64 + ty * 4];
            float4 b0 = *(const float4*)&Ws[kk][tx * 4];
            float4 b1 = *(const float4*)&Ws[kk][64 + tx * 4];
            float a[8]  = {a0.x, a0.y, a0.z, a0.w, a1.x, a1.y, a1.z, a1.w};
            float bv[8] = {b0.x, b0.y, b0.z, b0.w, b1.x, b1.y, b1.z, b1.w};
#pragma unroll
            for (int i = 0; i < 8; i++)
#pragma unroll
                for (int j = 0; j < 8; j++) acc[i][j] += a[i] * bv[j];
        }
        __syncthreads();
    }

    float4 pb0 = *(const float4*)(bias + n0 + tx * 4);
    float4 pb1 = *(const float4*)(bias + n0 + 64 + tx * 4);
#pragma unroll
    for (int i = 0; i < 8; i++) {
        int mrow = (i < 4) ? (ty * 4 + i) : (64 + ty * 4 + (i - 4));
        float* orow = out + (size_t)(m0 + mrow) * NC + n0;
        float4 v0 = make_float4(acc[i][0] + pb0.x, acc[i][1] + pb0.y,
                                acc[i][2] + pb0.z, acc[i][3] + pb0.w);
        float4 v1 = make_float4(acc[i][4] + pb1.x, acc[i][5] + pb1.y,
                                acc[i][6] + pb1.z, acc[i][7] + pb1.w);
        *(float4*)(orow + tx * 4)      = v0;
        *(float4*)(orow + 64 + tx * 4) = v1;
    }
}

// ---------------------------------------------------------------------------
extern "C" void kernel_launch(void* const* d_in, const int* in_sizes, int n_in,
                              void* d_out, int out_size)
{
    const float* x    = (const float*)d_in[0];
    const float* qw   = (const float*)d_in[1];
    const float* qb   = (const float*)d_in[2];
    const float* kvw  = (const float*)d_in[3];
    const float* kvb  = (const float*)d_in[4];
    const float* fcw  = (const float*)d_in[5];
    const float* fcb  = (const float*)d_in[6];
    const float* depw = (const float*)d_in[7];
    const float* depb = (const float*)d_in[8];
    const float* lng  = (const float*)d_in[9];
    const float* lnb  = (const float*)d_in[10];
    const float* pw   = (const float*)d_in[11];
    const float* pb   = (const float*)d_in[12];
    float* out = (float*)d_out;

    dim3 g1(9, 256);
    k_gemm_qkv<<<g1, 256>>>(x, qw, kvw, qb, kvb);

    dim3 g2(4, 64, 8);          // (row tiles, k=head-dim groups, batch)
    k_fc_conv<<<g2, 256>>>(fcw, fcb, depw, depb);

    dim3 g3(256, 8);            // (token tiles of 16, batch)
    k_ln_gelu<<<g3, 256>>>(lng, lnb);

    dim3 g4(3, 256);
    k_gemm_proj<<<g4, 256>>>(pw, pb, out);
}

// round 14
// speedup vs baseline: 1.5633x; 1.5633x over previous
#include <cuda_runtime.h>
#include <math.h>

// Problem constants
//  B=8, N=4096 (64x64), C=384, heads=6, d=64, G=3*heads=18
#define NB   8
#define NN   4096
#define NC   384
#define ND   64
#define NG   18

// Scratch (static device globals — allowed; no runtime allocation)
__device__ float g_qkv2[(size_t)NB * ND * NG * NN];   // 151 MB
__device__ float g_yc[(size_t)NB * NC * NN];          // 50 MB
__device__ float g_ya[(size_t)NB * NN * NC];          // 50 MB

// ---------------------------------------------------------------------------
// Packed f32x2 helpers (FFMA2 — 2x fp32 FMA throughput, exact fp32 math).
// ptxas never auto-fuses these; must come from PTX fma.rn.f32x2.
// ---------------------------------------------------------------------------
__device__ __forceinline__ unsigned long long pk2(float lo, float hi) {
    unsigned long long r;
    asm("mov.b64 %0, {%1, %2};" : "=l"(r) : "f"(lo), "f"(hi));
    return r;
}
__device__ __forceinline__ void fma2(unsigned long long& d,
                                     unsigned long long a,
                                     unsigned long long b) {
    asm("fma.rn.f32x2 %0, %1, %2, %0;" : "+l"(d) : "l"(a), "l"(b));
}
__device__ __forceinline__ float2 upk2(unsigned long long v) {
    float2 f;
    asm("mov.b64 {%0, %1}, %2;" : "=f"(f.x), "=f"(f.y) : "l"(v));
    return f;
}

// ---------------------------------------------------------------------------
// GEMM1: y3[m, oc] = x[m,:] . W3[oc,:] + b3[oc],  W3 = concat(q_w, kv_w)
// M = 32768, Nout = 1152, K = 384.  128x128x8 tiles, 8x8 per thread,
// inner product via packed FFMA2 (32 f32x2 ops per k-step per thread).
// Epilogue scatters into g_qkv2 via smem staging (coalesced 512B runs):
//   g = oc/64, k = oc%64  ->  g_qkv2[((b*64+k)*18+g)*4096 + n]
// ---------------------------------------------------------------------------
__global__ void __launch_bounds__(256) k_gemm_qkv(
    const float* __restrict__ x,
    const float* __restrict__ qw, const float* __restrict__ kvw,
    const float* __restrict__ qb, const float* __restrict__ kvb)
{
    const int K = NC;
    const int n0 = blockIdx.x * 128;   // 0..1024, step 128
    const int m0 = blockIdx.y * 128;

    const float* W;
    int nrow0;
    if (n0 < 384) { W = qw;  nrow0 = n0; }
    else          { W = kvw; nrow0 = n0 - 384; }

    __shared__ float As[8][132];
    __shared__ float Ws[8][132];
    __shared__ float Cs[128][17];

    const int tid  = threadIdx.x;
    const int tx   = tid & 15;
    const int ty   = tid >> 4;
    const int lrow = tid >> 1;
    const int lk4  = (tid & 1) * 4;

    const float* Ap = x + (size_t)(m0 + lrow) * K + lk4;
    const float* Wp = W + (size_t)(nrow0 + lrow) * K + lk4;

    unsigned long long acc2[8][4];
#pragma unroll
    for (int i = 0; i < 8; i++)
#pragma unroll
        for (int j = 0; j < 4; j++) acc2[i][j] = 0ull;

#pragma unroll 1
    for (int kt = 0; kt < K; kt += 8) {
        float4 av = *(const float4*)(Ap + kt);
        float4 wv = *(const float4*)(Wp + kt);
        As[lk4 + 0][lrow] = av.x; As[lk4 + 1][lrow] = av.y;
        As[lk4 + 2][lrow] = av.z; As[lk4 + 3][lrow] = av.w;
        Ws[lk4 + 0][lrow] = wv.x; Ws[lk4 + 1][lrow] = wv.y;
        Ws[lk4 + 2][lrow] = wv.z; Ws[lk4 + 3][lrow] = wv.w;
        __syncthreads();
#pragma unroll
        for (int kk = 0; kk < 8; kk++) {
            float4 a0 = *(const float4*)&As[kk][ty * 4];
            float4 a1 = *(const float4*)&As[kk][64 + ty * 4];
            float4 b0 = *(const float4*)&Ws[kk][tx * 4];
            float4 b1 = *(const float4*)&Ws[kk][64 + tx * 4];
            unsigned long long bp[4] = {
                pk2(b0.x, b0.y), pk2(b0.z, b0.w),
                pk2(b1.x, b1.y), pk2(b1.z, b1.w)
            };
            float a[8] = {a0.x, a0.y, a0.z, a0.w, a1.x, a1.y, a1.z, a1.w};
#pragma unroll
            for (int i = 0; i < 8; i++) {
                unsigned long long ap = pk2(a[i], a[i]);
#pragma unroll
                for (int jp = 0; jp < 4; jp++) fma2(acc2[i][jp], ap, bp[jp]);
            }
        }
        __syncthreads();
    }

    // Unpack to scalar accs (layout identical to pre-FFMA2 version)
    float acc[8][8];
#pragma unroll
    for (int i = 0; i < 8; i++)
#pragma unroll
        for (int jp = 0; jp < 4; jp++) {
            float2 u = upk2(acc2[i][jp]);
            acc[i][2 * jp]     = u.x;
            acc[i][2 * jp + 1] = u.y;
        }

    // Staged scatter epilogue: 8 passes of 128 rows x 16 cols through smem.
#pragma unroll 1
    for (int jj = 0; jj < 8; jj++) {
        const int half = jj >> 2;
        const int jl   = jj & 3;
#pragma unroll
        for (int i = 0; i < 8; i++) {
            int mrow = (i < 4) ? (ty * 4 + i) : (64 + ty * 4 + (i - 4));
            Cs[mrow][tx] = acc[i][half * 4 + jl];
        }
        __syncthreads();
#pragma unroll
        for (int p = tid; p < 2048; p += 256) {
            int col16 = p >> 7;
            int ml    = p & 127;
            int oc    = n0 + half * 64 + col16 * 4 + jl;      // 0..1151
            float bvv = (oc < 384) ? __ldg(qb + oc) : __ldg(kvb + oc - 384);
            int m = m0 + ml;
            int bi = m >> 12;        // batch
            int n  = m & 4095;       // token within batch
            int g  = oc >> 6;        // qkv group 0..17
            int kd = oc & 63;        // head-dim index
            g_qkv2[(((size_t)(bi * 64 + kd)) * 18 + g) * 4096 + n] = Cs[ml][col16] + bvv;
        }
        __syncthreads();
    }
}

// ---------------------------------------------------------------------------
// Fused 1x1 fc mix + grouped 3x3 conv.
// Block = (b, k, 16-row tile). Builds f[o=0..8][18 rows][66 cols] in smem
// directly from g_qkv2 (record m*18..m*18+17 per pixel), then 3x3 conv
// producing 6 output channels (oc = k*6+j), written channel-major to g_yc.
// Conv phase uses packed FFMA2 over channel pairs.
// ---------------------------------------------------------------------------
__global__ void __launch_bounds__(256) k_fc_conv(
    const float* __restrict__ fcw, const float* __restrict__ fcb,
    const float* __restrict__ depw, const float* __restrict__ depb)
{
    const int h0 = blockIdx.x * 16;
    const int k  = blockIdx.y;
    const int b  = blockIdx.z;

    __shared__ float fs[9][18][66];
    __shared__ float fw[162];   // fc_w [9][18]
    __shared__ float fb9[9];
    __shared__ unsigned long long wsp[81][3];  // dep_w packed channel pairs
    __shared__ float wb[6];

    const int tid = threadIdx.x;
    if (tid < 162) fw[tid] = fcw[tid];
    if (tid < 9)   fb9[tid] = fcb[tid];
    if (tid < 6)   wb[tid] = depb[k * 6 + tid];
    for (int p = tid; p < 243; p += 256) {
        int wi = p / 3;
        int pp = p % 3;
        float lo = depw[(size_t)(k * 6 + 2 * pp)     * 81 + wi];
        float hi = depw[(size_t)(k * 6 + 2 * pp + 1) * 81 + wi];
        wsp[wi][pp] = pk2(lo, hi);
    }

    float* fsf = &fs[0][0][0];
    for (int p = tid; p < 9 * 18 * 66; p += 256) fsf[p] = 0.f;
    __syncthreads();

    const float* base = g_qkv2 + ((size_t)(b * 64 + k)) * (NG * NN);

    // fc phase: 18 rows (h0-1 .. h0+16) x 64 cols; out-of-range rows stay 0.
    for (int p = tid; p < 18 * 64; p += 256) {
        int r = p >> 6;
        int c = p & 63;
        int h = h0 - 1 + r;
        if (h >= 0 && h < 64) {
            const float* src = base + (size_t)(h * 64 + c) * 18;
            float a9[9];
#pragma unroll
            for (int o = 0; o < 9; o++) a9[o] = fb9[o];
#pragma unroll
            for (int i = 0; i < 18; i++) {
                float v = src[i];
#pragma unroll
                for (int o = 0; o < 9; o++) a9[o] += fw[o * 18 + i] * v;
            }
#pragma unroll
            for (int o = 0; o < 9; o++) fs[o][r][c + 1] = a9[o];
        }
    }
    __syncthreads();

    // conv phase: each thread does 4 output rows x 1 col x 6 output channels,
    // accumulated as 3 packed channel pairs via FFMA2.
    const int c  = tid & 63;
    const int r0 = (tid >> 6) * 4;
    unsigned long long acc2[4][3];
#pragma unroll
    for (int rr = 0; rr < 4; rr++) {
        acc2[rr][0] = pk2(wb[0], wb[1]);
        acc2[rr][1] = pk2(wb[2], wb[3]);
        acc2[rr][2] = pk2(wb[4], wb[5]);
    }

#pragma unroll
    for (int o = 0; o < 9; o++) {
#pragma unroll
        for (int dy = 0; dy < 3; dy++) {
#pragma unroll
            for (int dx = 0; dx < 3; dx++) {
                const int wi = o * 9 + dy * 3 + dx;
                unsigned long long w0 = wsp[wi][0];
                unsigned long long w1 = wsp[wi][1];
                unsigned long long w2 = wsp[wi][2];
#pragma unroll
                for (int rr = 0; rr < 4; rr++) {
                    float fv = fs[o][r0 + rr + dy][c + dx];
                    unsigned long long fp = pk2(fv, fv);
                    fma2(acc2[rr][0], fp, w0);
                    fma2(acc2[rr][1], fp, w1);
                    fma2(acc2[rr][2], fp, w2);
                }
            }
        }
    }

#pragma unroll
    for (int jp = 0; jp < 3; jp++) {
        size_t ch0 = ((size_t)(b * NC + k * 6 + 2 * jp)) * NN;
        size_t ch1 = ch0 + NN;
#pragma unroll
        for (int rr = 0; rr < 4; rr++) {
            float2 u = upk2(acc2[rr][jp]);
            g_yc[ch0 + (h0 + r0 + rr) * 64 + c] = u.x;
            g_yc[ch1 + (h0 + r0 + rr) * 64 + c] = u.y;
        }
    }
}

// ---------------------------------------------------------------------------
// Transpose + LayerNorm + exact GELU.
// Block = (16 tokens, batch b). smem tile s[384][17] (conflict-free).
// ---------------------------------------------------------------------------
__global__ void __launch_bounds__(256) k_ln_gelu(
    const float* __restrict__ lng, const float* __restrict__ lnb)
{
    const int m0 = blockIdx.x * 16;
    const int b  = blockIdx.y;
    __shared__ float s[NC][17];

    const int tid = threadIdx.x;
    for (int p = tid; p < NC * 16; p += 256) {
        int ch = p >> 4;
        int ml = p & 15;
        s[ch][ml] = g_yc[((size_t)(b * NC + ch)) * NN + m0 + ml];
    }
    __syncthreads();

    const int w    = tid >> 5;
    const int lane = tid & 31;
#pragma unroll
    for (int tt = 0; tt < 2; tt++) {
        int t = w * 2 + tt;
        float sum = 0.f, sq = 0.f;
#pragma unroll
        for (int ch = lane; ch < NC; ch += 32) {
            float v = s[ch][t];
            sum += v;
            sq  += v * v;
        }
#pragma unroll
        for (int off = 16; off > 0; off >>= 1) {
            sum += __shfl_xor_sync(0xffffffffu, sum, off);
            sq  += __shfl_xor_sync(0xffffffffu, sq,  off);
        }
        float mean = sum * (1.f / NC);
        float var  = sq * (1.f / NC) - mean * mean;
        float rstd = rsqrtf(var + 1e-5f);
        size_t orow = ((size_t)(b * NN + m0 + t)) * NC;
#pragma unroll
        for (int ch = lane; ch < NC; ch += 32) {
            float v  = (s[ch][t] - mean) * rstd * __ldg(lng + ch) + __ldg(lnb + ch);
            float gl = 0.5f * v * (1.f + erff(v * 0.70710678118654752f));
            g_ya[orow + ch] = gl;
        }
    }
}

// ---------------------------------------------------------------------------
// GEMM2: out[m, c] = g_ya[m,:] . proj_w[c,:] + proj_b[c]
// M = 32768, Nout = 384, K = 384. Same tile scheme, FFMA2 inner product,
// float4 direct epilogue.
// ---------------------------------------------------------------------------
__global__ void __launch_bounds__(256) k_gemm_proj(
    const float* __restrict__ W, const float* __restrict__ bias,
    float* __restrict__ out)
{
    const int K  = NC;
    const int n0 = blockIdx.x * 128;
    const int m0 = blockIdx.y * 128;

    __shared__ float As[8][132];
    __shared__ float Ws[8][132];

    const int tid  = threadIdx.x;
    const int tx   = tid & 15;
    const int ty   = tid >> 4;
    const int lrow = tid >> 1;
    const int lk4  = (tid & 1) * 4;

    const float* Ap = g_ya + (size_t)(m0 + lrow) * K + lk4;
    const float* Wp = W    + (size_t)(n0 + lrow) * K + lk4;

    unsigned long long acc2[8][4];
#pragma unroll
    for (int i = 0; i < 8; i++)
#pragma unroll
        for (int j = 0; j < 4; j++) acc2[i][j] = 0ull;

#pragma unroll 1
    for (int kt = 0; kt < K; kt += 8) {
        float4 av = *(const float4*)(Ap + kt);
        float4 wv = *(const float4*)(Wp + kt);
        As[lk4 + 0][lrow] = av.x; As[lk4 + 1][lrow] = av.y;
        As[lk4 + 2][lrow] = av.z; As[lk4 + 3][lrow] = av.w;
        Ws[lk4 + 0][lrow] = wv.x; Ws[lk4 + 1][lrow] = wv.y;
        Ws[lk4 + 2][lrow] = wv.z; Ws[lk4 + 3][lrow] = wv.w;
        __syncthreads();
#pragma unroll
        for (int kk = 0; kk < 8; kk++) {
            float4 a0 = *(const float4*)&As[kk][ty * 4];
            float4 a1 = *(const float4*)&As[kk][64 + ty * 4];
            float4 b0 = *(const float4*)&Ws[kk][tx * 4];
            float4 b1 = *(const float4*)&Ws[kk][64 + tx * 4];
            unsigned long long bp[4] = {
                pk2(b0.x, b0.y), pk2(b0.z, b0.w),
                pk2(b1.x, b1.y), pk2(b1.z, b1.w)
            };
            float a[8] = {a0.x, a0.y, a0.z, a0.w, a1.x, a1.y, a1.z, a1.w};
#pragma unroll
            for (int i = 0; i < 8; i++) {
                unsigned long long ap = pk2(a[i], a[i]);
#pragma unroll
                for (int jp = 0; jp < 4; jp++) fma2(acc2[i][jp], ap, bp[jp]);
            }
        }
        __syncthreads();
    }

    float acc[8][8];
#pragma unroll
    for (int i = 0; i < 8; i++)
#pragma unroll
        for (int jp = 0; jp < 4; jp++) {
            float2 u = upk2(acc2[i][jp]);
            acc[i][2 * jp]     = u.x;
            acc[i][2 * jp + 1] = u.y;
        }

    float4 pb0 = *(const float4*)(bias + n0 + tx * 4);
    float4 pb1 = *(const float4*)(bias + n0 + 64 + tx * 4);
#pragma unroll
    for (int i = 0; i < 8; i++) {
        int mrow = (i < 4) ? (ty * 4 + i) : (64 + ty * 4 + (i - 4));
        float* orow = out + (size_t)(m0 + mrow) * NC + n0;
        float4 v0 = make_float4(acc[i][0] + pb0.x, acc[i][1] + pb0.y,
                                acc[i][2] + pb0.z, acc[i][3] + pb0.w);
        float4 v1 = make_float4(acc[i][4] + pb1.x, acc[i][5] + pb1.y,
                                acc[i][6] + pb1.z, acc[i][7] + pb1.w);
        *(float4*)(orow + tx * 4)      = v0;
        *(float4*)(orow + 64 + tx * 4) = v1;
    }
}

// ---------------------------------------------------------------------------
extern "C" void kernel_launch(void* const* d_in, const int* in_sizes, int n_in,
                              void* d_out, int out_size)
{
    const float* x    = (const float*)d_in[0];
    const float* qw   = (const float*)d_in[1];
    const float* qb   = (const float*)d_in[2];
    const float* kvw  = (const float*)d_in[3];
    const float* kvb  = (const float*)d_in[4];
    const float* fcw  = (const float*)d_in[5];
    const float* fcb  = (const float*)d_in[6];
    const float* depw = (const float*)d_in[7];
    const float* depb = (const float*)d_in[8];
    const float* lng  = (const float*)d_in[9];
    const float* lnb  = (const float*)d_in[10];
    const float* pw   = (const float*)d_in[11];
    const float* pb   = (const float*)d_in[12];
    float* out = (float*)d_out;

    dim3 g1(9, 256);
    k_gemm_qkv<<<g1, 256>>>(x, qw, kvw, qb, kvb);

    dim3 g2(4, 64, 8);          // (row tiles, k=head-dim groups, batch)
    k_fc_conv<<<g2, 256>>>(fcw, fcb, depw, depb);

    dim3 g3(256, 8);            // (token tiles of 16, batch)
    k_ln_gelu<<<g3, 256>>>(lng, lnb);

    dim3 g4(3, 256);
    k_gemm_proj<<<g4, 256>>>(pw, pb, out);
}

// round 15
// speedup vs baseline: 1.5649x; 1.0010x over previous
#include <cuda_runtime.h>
#include <math.h>

// Problem constants
//  B=8, N=4096 (64x64), C=384, heads=6, d=64, G=3*heads=18
#define NB   8
#define NN   4096
#define NC   384
#define ND   64
#define NG   18

// Scratch (static device globals — allowed; no runtime allocation)
__device__ float g_qkv2[(size_t)NB * ND * NG * NN];   // 151 MB
__device__ float g_yc[(size_t)NB * NC * NN];          // 50 MB
__device__ float g_ya[(size_t)NB * NN * NC];          // 50 MB

// ---------------------------------------------------------------------------
// Packed f32x2 helpers (FFMA2 — 2x fp32 FMA throughput, exact fp32 math).
// ptxas never auto-fuses these; must come from PTX fma.rn.f32x2.
// ---------------------------------------------------------------------------
__device__ __forceinline__ unsigned long long pk2(float lo, float hi) {
    unsigned long long r;
    asm("mov.b64 %0, {%1, %2};" : "=l"(r) : "f"(lo), "f"(hi));
    return r;
}
__device__ __forceinline__ void fma2(unsigned long long& d,
                                     unsigned long long a,
                                     unsigned long long b) {
    asm("fma.rn.f32x2 %0, %1, %2, %0;" : "+l"(d) : "l"(a), "l"(b));
}
__device__ __forceinline__ float2 upk2(unsigned long long v) {
    float2 f;
    asm("mov.b64 {%0, %1}, %2;" : "=f"(f.x), "=f"(f.y) : "l"(v));
    return f;
}

// ---------------------------------------------------------------------------
// GEMM1: y3[m, oc] = x[m,:] . W3[oc,:] + b3[oc],  W3 = concat(q_w, kv_w)
// M = 32768, Nout = 1152, K = 384.  128x128x8 tiles, 8x8 per thread,
// inner product via packed FFMA2 (32 f32x2 ops per k-step per thread).
// Epilogue scatters into g_qkv2 via smem staging (coalesced 512B runs):
//   g = oc/64, k = oc%64  ->  g_qkv2[((b*64+k)*18+g)*4096 + n]
// ---------------------------------------------------------------------------
__global__ void __launch_bounds__(256) k_gemm_qkv(
    const float* __restrict__ x,
    const float* __restrict__ qw, const float* __restrict__ kvw,
    const float* __restrict__ qb, const float* __restrict__ kvb)
{
    const int K = NC;
    const int n0 = blockIdx.x * 128;   // 0..1024, step 128
    const int m0 = blockIdx.y * 128;

    const float* W;
    int nrow0;
    if (n0 < 384) { W = qw;  nrow0 = n0; }
    else          { W = kvw; nrow0 = n0 - 384; }

    __shared__ float As[8][132];
    __shared__ float Ws[8][132];
    __shared__ float Cs[128][17];

    const int tid  = threadIdx.x;
    const int tx   = tid & 15;
    const int ty   = tid >> 4;
    const int lrow = tid >> 1;
    const int lk4  = (tid & 1) * 4;

    const float* Ap = x + (size_t)(m0 + lrow) * K + lk4;
    const float* Wp = W + (size_t)(nrow0 + lrow) * K + lk4;

    unsigned long long acc2[8][4];
#pragma unroll
    for (int i = 0; i < 8; i++)
#pragma unroll
        for (int j = 0; j < 4; j++) acc2[i][j] = 0ull;

#pragma unroll 1
    for (int kt = 0; kt < K; kt += 8) {
        float4 av = *(const float4*)(Ap + kt);
        float4 wv = *(const float4*)(Wp + kt);
        As[lk4 + 0][lrow] = av.x; As[lk4 + 1][lrow] = av.y;
        As[lk4 + 2][lrow] = av.z; As[lk4 + 3][lrow] = av.w;
        Ws[lk4 + 0][lrow] = wv.x; Ws[lk4 + 1][lrow] = wv.y;
        Ws[lk4 + 2][lrow] = wv.z; Ws[lk4 + 3][lrow] = wv.w;
        __syncthreads();
#pragma unroll
        for (int kk = 0; kk < 8; kk++) {
            float4 a0 = *(const float4*)&As[kk][ty * 4];
            float4 a1 = *(const float4*)&As[kk][64 + ty * 4];
            float4 b0 = *(const float4*)&Ws[kk][tx * 4];
            float4 b1 = *(const float4*)&Ws[kk][64 + tx * 4];
            unsigned long long bp[4] = {
                pk2(b0.x, b0.y), pk2(b0.z, b0.w),
                pk2(b1.x, b1.y), pk2(b1.z, b1.w)
            };
            float a[8] = {a0.x, a0.y, a0.z, a0.w, a1.x, a1.y, a1.z, a1.w};
#pragma unroll
            for (int i = 0; i < 8; i++) {
                unsigned long long ap = pk2(a[i], a[i]);
#pragma unroll
                for (int jp = 0; jp < 4; jp++) fma2(acc2[i][jp], ap, bp[jp]);
            }
        }
        __syncthreads();
    }

    // Unpack to scalar accs (layout identical to pre-FFMA2 version)
    float acc[8][8];
#pragma unroll
    for (int i = 0; i < 8; i++)
#pragma unroll
        for (int jp = 0; jp < 4; jp++) {
            float2 u = upk2(acc2[i][jp]);
            acc[i][2 * jp]     = u.x;
            acc[i][2 * jp + 1] = u.y;
        }

    // Staged scatter epilogue: 8 passes of 128 rows x 16 cols through smem.
#pragma unroll 1
    for (int jj = 0; jj < 8; jj++) {
        const int half = jj >> 2;
        const int jl   = jj & 3;
#pragma unroll
        for (int i = 0; i < 8; i++) {
            int mrow = (i < 4) ? (ty * 4 + i) : (64 + ty * 4 + (i - 4));
            Cs[mrow][tx] = acc[i][half * 4 + jl];
        }
        __syncthreads();
#pragma unroll
        for (int p = tid; p < 2048; p += 256) {
            int col16 = p >> 7;
            int ml    = p & 127;
            int oc    = n0 + half * 64 + col16 * 4 + jl;      // 0..1151
            float bvv = (oc < 384) ? __ldg(qb + oc) : __ldg(kvb + oc - 384);
            int m = m0 + ml;
            int bi = m >> 12;        // batch
            int n  = m & 4095;       // token within batch
            int g  = oc >> 6;        // qkv group 0..17
            int kd = oc & 63;        // head-dim index
            g_qkv2[(((size_t)(bi * 64 + kd)) * 18 + g) * 4096 + n] = Cs[ml][col16] + bvv;
        }
        __syncthreads();
    }
}

// ---------------------------------------------------------------------------
// Fused 1x1 fc mix + grouped 3x3 conv.
// Block = (b, k, 16-row tile). Builds f[o=0..8][18 rows][66 cols] in smem
// directly from g_qkv2 (record m*18..m*18+17 per pixel), then 3x3 conv
// producing 6 output channels (oc = k*6+j), written channel-major to g_yc.
// Conv phase uses packed FFMA2 over channel pairs.
// ---------------------------------------------------------------------------
__global__ void __launch_bounds__(256) k_fc_conv(
    const float* __restrict__ fcw, const float* __restrict__ fcb,
    const float* __restrict__ depw, const float* __restrict__ depb)
{
    const int h0 = blockIdx.x * 16;
    const int k  = blockIdx.y;
    const int b  = blockIdx.z;

    __shared__ float fs[9][18][66];
    __shared__ float fw[162];   // fc_w [9][18]
    __shared__ float fb9[9];
    __shared__ unsigned long long wsp[81][3];  // dep_w packed channel pairs
    __shared__ float wb[6];

    const int tid = threadIdx.x;
    if (tid < 162) fw[tid] = fcw[tid];
    if (tid < 9)   fb9[tid] = fcb[tid];
    if (tid < 6)   wb[tid] = depb[k * 6 + tid];
    for (int p = tid; p < 243; p += 256) {
        int wi = p / 3;
        int pp = p % 3;
        float lo = depw[(size_t)(k * 6 + 2 * pp)     * 81 + wi];
        float hi = depw[(size_t)(k * 6 + 2 * pp + 1) * 81 + wi];
        wsp[wi][pp] = pk2(lo, hi);
    }

    float* fsf = &fs[0][0][0];
    for (int p = tid; p < 9 * 18 * 66; p += 256) fsf[p] = 0.f;
    __syncthreads();

    const float* base = g_qkv2 + ((size_t)(b * 64 + k)) * (NG * NN);

    // fc phase: 18 rows (h0-1 .. h0+16) x 64 cols; out-of-range rows stay 0.
    for (int p = tid; p < 18 * 64; p += 256) {
        int r = p >> 6;
        int c = p & 63;
        int h = h0 - 1 + r;
        if (h >= 0 && h < 64) {
            const float* src = base + (size_t)(h * 64 + c) * 18;
            float a9[9];
#pragma unroll
            for (int o = 0; o < 9; o++) a9[o] = fb9[o];
#pragma unroll
            for (int i = 0; i < 18; i++) {
                float v = src[i];
#pragma unroll
                for (int o = 0; o < 9; o++) a9[o] += fw[o * 18 + i] * v;
            }
#pragma unroll
            for (int o = 0; o < 9; o++) fs[o][r][c + 1] = a9[o];
        }
    }
    __syncthreads();

    // conv phase: each thread does 4 output rows x 1 col x 6 output channels,
    // accumulated as 3 packed channel pairs via FFMA2.
    const int c  = tid & 63;
    const int r0 = (tid >> 6) * 4;
    unsigned long long acc2[4][3];
#pragma unroll
    for (int rr = 0; rr < 4; rr++) {
        acc2[rr][0] = pk2(wb[0], wb[1]);
        acc2[rr][1] = pk2(wb[2], wb[3]);
        acc2[rr][2] = pk2(wb[4], wb[5]);
    }

#pragma unroll
    for (int o = 0; o < 9; o++) {
#pragma unroll
        for (int dy = 0; dy < 3; dy++) {
#pragma unroll
            for (int dx = 0; dx < 3; dx++) {
                const int wi = o * 9 + dy * 3 + dx;
                unsigned long long w0 = wsp[wi][0];
                unsigned long long w1 = wsp[wi][1];
                unsigned long long w2 = wsp[wi][2];
#pragma unroll
                for (int rr = 0; rr < 4; rr++) {
                    float fv = fs[o][r0 + rr + dy][c + dx];
                    unsigned long long fp = pk2(fv, fv);
                    fma2(acc2[rr][0], fp, w0);
                    fma2(acc2[rr][1], fp, w1);
                    fma2(acc2[rr][2], fp, w2);
                }
            }
        }
    }

#pragma unroll
    for (int jp = 0; jp < 3; jp++) {
        size_t ch0 = ((size_t)(b * NC + k * 6 + 2 * jp)) * NN;
        size_t ch1 = ch0 + NN;
#pragma unroll
        for (int rr = 0; rr < 4; rr++) {
            float2 u = upk2(acc2[rr][jp]);
            g_yc[ch0 + (h0 + r0 + rr) * 64 + c] = u.x;
            g_yc[ch1 + (h0 + r0 + rr) * 64 + c] = u.y;
        }
    }
}

// ---------------------------------------------------------------------------
// Transpose + LayerNorm + exact GELU.
// Block = (16 tokens, batch b). smem tile s[384][17] (conflict-free).
// ---------------------------------------------------------------------------
__global__ void __launch_bounds__(256) k_ln_gelu(
    const float* __restrict__ lng, const float* __restrict__ lnb)
{
    const int m0 = blockIdx.x * 16;
    const int b  = blockIdx.y;
    __shared__ float s[NC][17];

    const int tid = threadIdx.x;
    for (int p = tid; p < NC * 16; p += 256) {
        int ch = p >> 4;
        int ml = p & 15;
        s[ch][ml] = g_yc[((size_t)(b * NC + ch)) * NN + m0 + ml];
    }
    __syncthreads();

    const int w    = tid >> 5;
    const int lane = tid & 31;
#pragma unroll
    for (int tt = 0; tt < 2; tt++) {
        int t = w * 2 + tt;
        float sum = 0.f, sq = 0.f;
#pragma unroll
        for (int ch = lane; ch < NC; ch += 32) {
            float v = s[ch][t];
            sum += v;
            sq  += v * v;
        }
#pragma unroll
        for (int off = 16; off > 0; off >>= 1) {
            sum += __shfl_xor_sync(0xffffffffu, sum, off);
            sq  += __shfl_xor_sync(0xffffffffu, sq,  off);
        }
        float mean = sum * (1.f / NC);
        float var  = sq * (1.f / NC) - mean * mean;
        float rstd = rsqrtf(var + 1e-5f);
        size_t orow = ((size_t)(b * NN + m0 + t)) * NC;
#pragma unroll
        for (int ch = lane; ch < NC; ch += 32) {
            float v  = (s[ch][t] - mean) * rstd * __ldg(lng + ch) + __ldg(lnb + ch);
            float gl = 0.5f * v * (1.f + erff(v * 0.70710678118654752f));
            g_ya[orow + ch] = gl;
        }
    }
}

// ---------------------------------------------------------------------------
// GEMM2: out[m, c] = g_ya[m,:] . proj_w[c,:] + proj_b[c]
// M = 32768, Nout = 384, K = 384. Same tile scheme, FFMA2 inner product,
// float4 direct epilogue.
// ---------------------------------------------------------------------------
__global__ void __launch_bounds__(256) k_gemm_proj(
    const float* __restrict__ W, const float* __restrict__ bias,
    float* __restrict__ out)
{
    const int K  = NC;
    const int n0 = blockIdx.x * 128;
    const int m0 = blockIdx.y * 128;

    __shared__ float As[8][132];
    __shared__ float Ws[8][132];

    const int tid  = threadIdx.x;
    const int tx   = tid & 15;
    const int ty   = tid >> 4;
    const int lrow = tid >> 1;
    const int lk4  = (tid & 1) * 4;

    const float* Ap = g_ya + (size_t)(m0 + lrow) * K + lk4;
    const float* Wp = W    + (size_t)(n0 + lrow) * K + lk4;

    unsigned long long acc2[8][4];
#pragma unroll
    for (int i = 0; i < 8; i++)
#pragma unroll
        for (int j = 0; j < 4; j++) acc2[i][j] = 0ull;

#pragma unroll 1
    for (int kt = 0; kt < K; kt += 8) {
        float4 av = *(const float4*)(Ap + kt);
        float4 wv = *(const float4*)(Wp + kt);
        As[lk4 + 0][lrow] = av.x; As[lk4 + 1][lrow] = av.y;
        As[lk4 + 2][lrow] = av.z; As[lk4 + 3][lrow] = av.w;
        Ws[lk4 + 0][lrow] = wv.x; Ws[lk4 + 1][lrow] = wv.y;
        Ws[lk4 + 2][lrow] = wv.z; Ws[lk4 + 3][lrow] = wv.w;
        __syncthreads();
#pragma unroll
        for (int kk = 0; kk < 8; kk++) {
            float4 a0 = *(const float4*)&As[kk][ty * 4];
            float4 a1 = *(const float4*)&As[kk][64 + ty * 4];
            float4 b0 = *(const float4*)&Ws[kk][tx * 4];
            float4 b1 = *(const float4*)&Ws[kk][64 + tx * 4];
            unsigned long long bp[4] = {
                pk2(b0.x, b0.y), pk2(b0.z, b0.w),
                pk2(b1.x, b1.y), pk2(b1.z, b1.w)
            };
            float a[8] = {a0.x, a0.y, a0.z, a0.w, a1.x, a1.y, a1.z, a1.w};
#pragma unroll
            for (int i = 0; i < 8; i++) {
                unsigned long long ap = pk2(a[i], a[i]);
#pragma unroll
                for (int jp = 0; jp < 4; jp++) fma2(acc2[i][jp], ap, bp[jp]);
            }
        }
        __syncthreads();
    }

    float acc[8][8];
#pragma unroll
    for (int i = 0; i < 8; i++)
#pragma unroll
        for (int jp = 0; jp < 4; jp++) {
            float2 u = upk2(acc2[i][jp]);
            acc[i][2 * jp]     = u.x;
            acc[i][2 * jp + 1] = u.y;
        }

    float4 pb0 = *(const float4*)(bias + n0 + tx * 4);
    float4 pb1 = *(const float4*)(bias + n0 + 64 + tx * 4);
#pragma unroll
    for (int i = 0; i < 8; i++) {
        int mrow = (i < 4) ? (ty * 4 + i) : (64 + ty * 4 + (i - 4));
        float* orow = out + (size_t)(m0 + mrow) * NC + n0;
        float4 v0 = make_float4(acc[i][0] + pb0.x, acc[i][1] + pb0.y,
                                acc[i][2] + pb0.z, acc[i][3] + pb0.w);
        float4 v1 = make_float4(acc[i][4] + pb1.x, acc[i][5] + pb1.y,
                                acc[i][6] + pb1.z, acc[i][7] + pb1.w);
        *(float4*)(orow + tx * 4)      = v0;
        *(float4*)(orow + 64 + tx * 4) = v1;
    }
}

// ---------------------------------------------------------------------------
extern "C" void kernel_launch(void* const* d_in, const int* in_sizes, int n_in,
                              void* d_out, int out_size)
{
    const float* x    = (const float*)d_in[0];
    const float* qw   = (const float*)d_in[1];
    const float* qb   = (const float*)d_in[2];
    const float* kvw  = (const float*)d_in[3];
    const float* kvb  = (const float*)d_in[4];
    const float* fcw  = (const float*)d_in[5];
    const float* fcb  = (const float*)d_in[6];
    const float* depw = (const float*)d_in[7];
    const float* depb = (const float*)d_in[8];
    const float* lng  = (const float*)d_in[9];
    const float* lnb  = (const float*)d_in[10];
    const float* pw   = (const float*)d_in[11];
    const float* pb   = (const float*)d_in[12];
    float* out = (float*)d_out;

    dim3 g1(9, 256);
    k_gemm_qkv<<<g1, 256>>>(x, qw, kvw, qb, kvb);

    dim3 g2(4, 64, 8);          // (row tiles, k=head-dim groups, batch)
    k_fc_conv<<<g2, 256>>>(fcw, fcb, depw, depb);

    dim3 g3(256, 8);            // (token tiles of 16, batch)
    k_ln_gelu<<<g3, 256>>>(lng, lnb);

    dim3 g4(3, 256);
    k_gemm_proj<<<g4, 256>>>(pw, pb, out);
}